// round 2
// baseline (speedup 1.0000x reference)
#include <cuda_runtime.h>
#include <cuda_bf16.h>

// auxiliary_loss: loss = 0.2 * (pos*sum_neg - neg*sum_pos) / (pos*neg)
// Triple reduction sum(y), sum(y*lab), sum(lab) fused into ONE kernel with
// last-block finalize (kills the 7.8us second-launch overhead seen in R1).

#define DETA 0.2

constexpr int RED_BLOCKS  = 1184;   // 148 SMs * 8 CTAs
constexpr int RED_THREADS = 256;

// Scratch (__device__ globals; no allocation).
__device__ float        g_psum_all[RED_BLOCKS];
__device__ float        g_psum_pos[RED_BLOCKS];
__device__ int          g_pcnt[RED_BLOCKS];
__device__ unsigned int g_done = 0;   // reset to 0 by the last block each call

__device__ __forceinline__ float warp_red_f(float v) {
    #pragma unroll
    for (int o = 16; o > 0; o >>= 1) v += __shfl_down_sync(0xffffffffu, v, o);
    return v;
}
__device__ __forceinline__ int warp_red_i(int v) {
    #pragma unroll
    for (int o = 16; o > 0; o >>= 1) v += __shfl_down_sync(0xffffffffu, v, o);
    return v;
}
__device__ __forceinline__ double warp_red_d(double v) {
    #pragma unroll
    for (int o = 16; o > 0; o >>= 1) v += __shfl_down_sync(0xffffffffu, v, o);
    return v;
}

__device__ __forceinline__ void accum4(const float4& v, const int4& l,
                                       float& sa, float& sp, int& c) {
    sa += (v.x + v.y) + (v.z + v.w);
    float p = 0.0f;
    if (l.x) p += v.x;
    if (l.y) p += v.y;
    if (l.z) p += v.z;
    if (l.w) p += v.w;
    sp += p;
    c  += l.x + l.y + l.z + l.w;
}

__global__ __launch_bounds__(RED_THREADS)
void fused_loss_kernel(const float4* __restrict__ y4,
                       const int4*   __restrict__ l4,
                       long long nvec,
                       const float* __restrict__ ytail,
                       const int*   __restrict__ ltail,
                       int tail,
                       float* __restrict__ out,
                       double n_total)
{
    float sa = 0.0f, sp = 0.0f;
    int   c  = 0;

    const long long stride = (long long)gridDim.x * blockDim.x;
    long long i = (long long)blockIdx.x * blockDim.x + threadIdx.x;

    // 4-way unrolled main loop: 8 independent 16B loads in flight per thread.
    for (; i + 3 * stride < nvec; i += 4 * stride) {
        float4 v0 = y4[i];
        float4 v1 = y4[i +     stride];
        float4 v2 = y4[i + 2 * stride];
        float4 v3 = y4[i + 3 * stride];
        int4   l0 = l4[i];
        int4   l1 = l4[i +     stride];
        int4   l2 = l4[i + 2 * stride];
        int4   l3 = l4[i + 3 * stride];
        accum4(v0, l0, sa, sp, c);
        accum4(v1, l1, sa, sp, c);
        accum4(v2, l2, sa, sp, c);
        accum4(v3, l3, sa, sp, c);
    }
    for (; i < nvec; i += stride) {
        float4 v = y4[i];
        int4   l = l4[i];
        accum4(v, l, sa, sp, c);
    }

    // Scalar tail (n % 4), handled once by block 0.
    if (blockIdx.x == 0 && (int)threadIdx.x < tail) {
        float v = ytail[threadIdx.x];
        int   l = ltail[threadIdx.x];
        sa += v;
        if (l) { sp += v; c += 1; }
    }

    // Intra-block reduce (fp32 partials -> block partial)
    sa = warp_red_f(sa);
    sp = warp_red_f(sp);
    c  = warp_red_i(c);

    __shared__ float s_sa[RED_THREADS / 32];
    __shared__ float s_sp[RED_THREADS / 32];
    __shared__ int   s_c [RED_THREADS / 32];
    __shared__ bool  s_last;
    int wid = threadIdx.x >> 5;
    int lid = threadIdx.x & 31;
    if (lid == 0) { s_sa[wid] = sa; s_sp[wid] = sp; s_c[wid] = c; }
    __syncthreads();

    if (wid == 0) {
        constexpr int NW = RED_THREADS / 32;
        float a = (lid < NW) ? s_sa[lid] : 0.0f;
        float p = (lid < NW) ? s_sp[lid] : 0.0f;
        int   k = (lid < NW) ? s_c [lid] : 0;
        a = warp_red_f(a);
        p = warp_red_f(p);
        k = warp_red_i(k);
        if (lid == 0) {
            g_psum_all[blockIdx.x] = a;
            g_psum_pos[blockIdx.x] = p;
            g_pcnt[blockIdx.x]     = k;
            __threadfence();
            unsigned int t = atomicAdd(&g_done, 1u);
            s_last = (t == (unsigned int)(gridDim.x - 1));
        }
    }
    __syncthreads();

    if (!s_last) return;

    // ---- Last block: finalize (partials are L2-hot). Deterministic order. ----
    double dsa = 0.0, dsp = 0.0;
    long long dc = 0;
    for (int j = threadIdx.x; j < RED_BLOCKS; j += RED_THREADS) {
        dsa += (double)g_psum_all[j];
        dsp += (double)g_psum_pos[j];
        dc  += (long long)g_pcnt[j];
    }
    dsa = warp_red_d(dsa);
    dsp = warp_red_d(dsp);
    #pragma unroll
    for (int o = 16; o > 0; o >>= 1) dc += __shfl_down_sync(0xffffffffu, dc, o);

    __shared__ double d_sa[RED_THREADS / 32], d_sp[RED_THREADS / 32];
    __shared__ long long d_c[RED_THREADS / 32];
    if (lid == 0) { d_sa[wid] = dsa; d_sp[wid] = dsp; d_c[wid] = dc; }
    __syncthreads();

    if (threadIdx.x == 0) {
        double SA = 0.0, SP = 0.0;
        long long C = 0;
        #pragma unroll
        for (int j = 0; j < RED_THREADS / 32; j++) { SA += d_sa[j]; SP += d_sp[j]; C += d_c[j]; }

        double pos = (double)C;
        double neg = n_total - pos;
        bool valid = (pos > 0.0) && (neg > 0.0);
        double sum_neg = SA - SP;
        double denom = valid ? pos * neg : 1.0;
        double loss = DETA * (pos * sum_neg - neg * SP) / denom;
        out[0] = valid ? (float)loss : 0.0f;

        g_done = 0;   // reset for next graph replay
    }
}

extern "C" void kernel_launch(void* const* d_in, const int* in_sizes, int n_in,
                              void* d_out, int out_size)
{
    const float* y   = (const float*)d_in[0];
    const int*   lab = (const int*)d_in[1];
    int n = in_sizes[0];

    long long nvec = (long long)(n >> 2);
    int tail = n & 3;
    const float* ytail = y + (nvec << 2);
    const int*   ltail = lab + (nvec << 2);

    fused_loss_kernel<<<RED_BLOCKS, RED_THREADS>>>(
        (const float4*)y, (const int4*)lab, nvec, ytail, ltail, tail,
        (float*)d_out, (double)n);
}

// round 3
// speedup vs baseline: 1.0973x; 1.0973x over previous
#include <cuda_runtime.h>
#include <cuda_bf16.h>

// auxiliary_loss: loss = 0.2 * (pos*sum_neg - neg*sum_pos) / (pos*neg)
// Single fused kernel: triple reduction sum(y), sum(y*lab), sum(lab) with
// last-block finalize. R3: 2-way unroll w/ independent accumulators,
// 32-bit indexing (R2's 4-way strided unroll + 64-bit math regressed).

#define DETA 0.2

constexpr int RED_BLOCKS  = 1184;   // 148 SMs * 8 CTAs
constexpr int RED_THREADS = 256;

// Scratch (__device__ globals; no allocation).
__device__ float        g_psum_all[RED_BLOCKS];
__device__ float        g_psum_pos[RED_BLOCKS];
__device__ int          g_pcnt[RED_BLOCKS];
__device__ unsigned int g_done = 0;   // reset by last block each call

__device__ __forceinline__ float warp_red_f(float v) {
    #pragma unroll
    for (int o = 16; o > 0; o >>= 1) v += __shfl_down_sync(0xffffffffu, v, o);
    return v;
}
__device__ __forceinline__ int warp_red_i(int v) {
    #pragma unroll
    for (int o = 16; o > 0; o >>= 1) v += __shfl_down_sync(0xffffffffu, v, o);
    return v;
}
__device__ __forceinline__ double warp_red_d(double v) {
    #pragma unroll
    for (int o = 16; o > 0; o >>= 1) v += __shfl_down_sync(0xffffffffu, v, o);
    return v;
}

__global__ __launch_bounds__(RED_THREADS)
void fused_loss_kernel(const float4* __restrict__ y4,
                       const int4*   __restrict__ l4,
                       int nvec,
                       const float* __restrict__ ytail,
                       const int*   __restrict__ ltail,
                       int tail,
                       float* __restrict__ out,
                       double n_total)
{
    // Independent accumulator pairs to break FADD dependency chains.
    float sa0 = 0.0f, sa1 = 0.0f, sp0 = 0.0f, sp1 = 0.0f;
    int   c0  = 0,    c1  = 0;

    const int stride = gridDim.x * blockDim.x;            // 303104, fits int
    int i = blockIdx.x * blockDim.x + threadIdx.x;

    // 2-way unrolled grid-stride: 4 independent 16B loads in flight.
    for (; i + stride < nvec; i += 2 * stride) {
        float4 v0 = y4[i];
        int4   l0 = l4[i];
        float4 v1 = y4[i + stride];
        int4   l1 = l4[i + stride];

        sa0 += (v0.x + v0.y) + (v0.z + v0.w);
        sa1 += (v1.x + v1.y) + (v1.z + v1.w);
        float p0 = 0.0f, p1 = 0.0f;
        if (l0.x) p0 += v0.x;
        if (l0.y) p0 += v0.y;
        if (l0.z) p0 += v0.z;
        if (l0.w) p0 += v0.w;
        if (l1.x) p1 += v1.x;
        if (l1.y) p1 += v1.y;
        if (l1.z) p1 += v1.z;
        if (l1.w) p1 += v1.w;
        sp0 += p0; sp1 += p1;
        c0  += l0.x + l0.y + l0.z + l0.w;
        c1  += l1.x + l1.y + l1.z + l1.w;
    }
    if (i < nvec) {
        float4 v = y4[i];
        int4   l = l4[i];
        sa0 += (v.x + v.y) + (v.z + v.w);
        float p = 0.0f;
        if (l.x) p += v.x;
        if (l.y) p += v.y;
        if (l.z) p += v.z;
        if (l.w) p += v.w;
        sp0 += p;
        c0  += l.x + l.y + l.z + l.w;
    }

    float sa = sa0 + sa1;
    float sp = sp0 + sp1;
    int   c  = c0 + c1;

    // Scalar tail (n % 4), handled once by block 0.
    if (blockIdx.x == 0 && (int)threadIdx.x < tail) {
        float v = ytail[threadIdx.x];
        int   l = ltail[threadIdx.x];
        sa += v;
        if (l) { sp += v; c += 1; }
    }

    // Intra-block reduce
    sa = warp_red_f(sa);
    sp = warp_red_f(sp);
    c  = warp_red_i(c);

    __shared__ float s_sa[RED_THREADS / 32];
    __shared__ float s_sp[RED_THREADS / 32];
    __shared__ int   s_c [RED_THREADS / 32];
    __shared__ bool  s_last;
    int wid = threadIdx.x >> 5;
    int lid = threadIdx.x & 31;
    if (lid == 0) { s_sa[wid] = sa; s_sp[wid] = sp; s_c[wid] = c; }
    __syncthreads();

    if (wid == 0) {
        constexpr int NW = RED_THREADS / 32;
        float a = (lid < NW) ? s_sa[lid] : 0.0f;
        float p = (lid < NW) ? s_sp[lid] : 0.0f;
        int   k = (lid < NW) ? s_c [lid] : 0;
        a = warp_red_f(a);
        p = warp_red_f(p);
        k = warp_red_i(k);
        if (lid == 0) {
            g_psum_all[blockIdx.x] = a;
            g_psum_pos[blockIdx.x] = p;
            g_pcnt[blockIdx.x]     = k;
            __threadfence();
            unsigned int t = atomicAdd(&g_done, 1u);
            s_last = (t == (unsigned int)(gridDim.x - 1));
        }
    }
    __syncthreads();

    if (!s_last) return;

    // ---- Last block: finalize (partials L2-hot). Deterministic order. ----
    double dsa = 0.0, dsp = 0.0;
    long long dc = 0;
    for (int j = threadIdx.x; j < RED_BLOCKS; j += RED_THREADS) {
        dsa += (double)g_psum_all[j];
        dsp += (double)g_psum_pos[j];
        dc  += (long long)g_pcnt[j];
    }
    dsa = warp_red_d(dsa);
    dsp = warp_red_d(dsp);
    #pragma unroll
    for (int o = 16; o > 0; o >>= 1) dc += __shfl_down_sync(0xffffffffu, dc, o);

    __shared__ double d_sa[RED_THREADS / 32], d_sp[RED_THREADS / 32];
    __shared__ long long d_c[RED_THREADS / 32];
    if (lid == 0) { d_sa[wid] = dsa; d_sp[wid] = dsp; d_c[wid] = dc; }
    __syncthreads();

    if (threadIdx.x == 0) {
        double SA = 0.0, SP = 0.0;
        long long C = 0;
        #pragma unroll
        for (int j = 0; j < RED_THREADS / 32; j++) { SA += d_sa[j]; SP += d_sp[j]; C += d_c[j]; }

        double pos = (double)C;
        double neg = n_total - pos;
        bool valid = (pos > 0.0) && (neg > 0.0);
        double sum_neg = SA - SP;
        double denom = valid ? pos * neg : 1.0;
        double loss = DETA * (pos * sum_neg - neg * SP) / denom;
        out[0] = valid ? (float)loss : 0.0f;

        g_done = 0;   // reset for next graph replay
    }
}

extern "C" void kernel_launch(void* const* d_in, const int* in_sizes, int n_in,
                              void* d_out, int out_size)
{
    const float* y   = (const float*)d_in[0];
    const int*   lab = (const int*)d_in[1];
    int n = in_sizes[0];

    int nvec = n >> 2;
    int tail = n & 3;
    const float* ytail = y + ((long long)nvec << 2);
    const int*   ltail = lab + ((long long)nvec << 2);

    fused_loss_kernel<<<RED_BLOCKS, RED_THREADS>>>(
        (const float4*)y, (const int4*)lab, nvec, ytail, ltail, tail,
        (float*)d_out, (double)n);
}